// round 3
// baseline (speedup 1.0000x reference)
#include <cuda_runtime.h>
#include <cuda_bf16.h>
#include <cstdint>

// Problem constants
#define BATCH   512
#define DIMC    64
#define BOOK    1024
#define EMB     64
#define CWDIM   (DIMC * EMB)            // 4096

// Output layout (floats): cw | one_hot | new_codebook | new_ema
#define CW_OFF    0
#define CW_SIZE   (BATCH * CWDIM)
#define OH_OFF    (CW_OFF + CW_SIZE)
#define OH_SIZE   (BATCH * DIMC * BOOK)              // 33,554,432
#define NCB_OFF   (OH_OFF + OH_SIZE)
#define NCB_SIZE  (DIMC * BOOK * EMB)                // 4,194,304
#define NEMA_OFF  (NCB_OFF + NCB_SIZE)
#define NEMA_SIZE (DIMC * BOOK)

// Scratch
__device__ __nv_bfloat16 g_xs[3][DIMC][BATCH][EMB];   // 12.6 MB
__device__ __nv_bfloat16 g_cs[3][DIMC][BOOK][EMB];    // 25 MB
__device__ float g_bsq[DIMC * BOOK];
__device__ unsigned long long g_key[BATCH * DIMC];    // (sortable_dist<<32)|k

static __device__ __forceinline__ uint32_t smem_u32(const void* p) {
    uint32_t a;
    asm("{ .reg .u64 t; cvta.to.shared.u64 t, %1; cvt.u32.u64 %0, t; }"
        : "=r"(a) : "l"(p));
    return a;
}

static __device__ __forceinline__ void split3(float v, __nv_bfloat16& h,
                                              __nv_bfloat16& m, __nv_bfloat16& l) {
    h = __float2bfloat16(v);
    float r = v - __bfloat162float(h);
    m = __float2bfloat16(r);
    float r2 = r - __bfloat162float(m);
    l = __float2bfloat16(r2);
}

#define LDSM_X4(r0, r1, r2, r3, a)                                       \
    asm volatile("ldmatrix.sync.aligned.m8n8.x4.shared.b16 "             \
                 "{%0,%1,%2,%3}, [%4];"                                  \
                 : "=r"(r0), "=r"(r1), "=r"(r2), "=r"(r3) : "r"(a))

#define MMA16816(c, a, b)                                                \
    asm volatile("mma.sync.aligned.m16n8k16.row.col.f32.bf16.bf16.f32 "  \
                 "{%0,%1,%2,%3}, {%4,%5,%6,%7}, {%8,%9}, {%0,%1,%2,%3};" \
                 : "+f"((c)[0]), "+f"((c)[1]), "+f"((c)[2]), "+f"((c)[3])\
                 : "r"((a)[0]), "r"((a)[1]), "r"((a)[2]), "r"((a)[3]),   \
                   "r"((b)[0]), "r"((b)[1]))

// ---------------------------------------------------------------------------
// Kernel 0: bf16x3 splits of x and codebook, |c|^2, and g_key init.
// One warp per 64-element row; lane handles 2 elements.
// ---------------------------------------------------------------------------
__global__ void __launch_bounds__(256)
split_kernel(const float* __restrict__ x, const float* __restrict__ cb)
{
    if (blockIdx.x < 128)
        g_key[blockIdx.x * 256 + threadIdx.x] = 0xFFFFFFFFFFFFFFFFull;

    int gw   = (blockIdx.x * 256 + threadIdx.x) >> 5;
    int lane = threadIdx.x & 31;
    int e0   = lane * 2;

    if (gw < DIMC * BATCH) {
        int d = gw >> 9, b = gw & 511;
        float2 v = *(const float2*)(x + (size_t)b * CWDIM + d * EMB + e0);
        __nv_bfloat16 h0, m0, l0, h1, m1, l1;
        split3(v.x, h0, m0, l0);
        split3(v.y, h1, m1, l1);
        size_t o = ((size_t)d * BATCH + b) * EMB + e0;
        __nv_bfloat162 t0; t0.x = h0; t0.y = h1;
        __nv_bfloat162 t1; t1.x = m0; t1.y = m1;
        __nv_bfloat162 t2; t2.x = l0; t2.y = l1;
        *(__nv_bfloat162*)(&g_xs[0][0][0][0] + o) = t0;
        *(__nv_bfloat162*)(&g_xs[1][0][0][0] + o) = t1;
        *(__nv_bfloat162*)(&g_xs[2][0][0][0] + o) = t2;
    } else {
        int r = gw - DIMC * BATCH;                 // d*1024 + k
        float2 v = *(const float2*)(cb + (size_t)r * EMB + e0);
        __nv_bfloat16 h0, m0, l0, h1, m1, l1;
        split3(v.x, h0, m0, l0);
        split3(v.y, h1, m1, l1);
        size_t o = (size_t)r * EMB + e0;
        __nv_bfloat162 t0; t0.x = h0; t0.y = h1;
        __nv_bfloat162 t1; t1.x = m0; t1.y = m1;
        __nv_bfloat162 t2; t2.x = l0; t2.y = l1;
        *(__nv_bfloat162*)(&g_cs[0][0][0][0] + o) = t0;
        *(__nv_bfloat162*)(&g_cs[1][0][0][0] + o) = t1;
        *(__nv_bfloat162*)(&g_cs[2][0][0][0] + o) = t2;
        float s = v.x * v.x + v.y * v.y;
        #pragma unroll
        for (int off = 16; off; off >>= 1)
            s += __shfl_xor_sync(0xffffffffu, s, off);
        if (lane == 0) g_bsq[r] = s;
    }
}

// ---------------------------------------------------------------------------
// Kernel 1: per (d, 128-row, 128-code) tile distance argmin via HMMA bf16x3
// (6 passes, fp32 accum), fused with one_hot zero + ncb/nema init.
// 256 threads = 8 warps (2M x 4N), warp tile 64x32.
// SMEM: A 128 rows x 400B (3 terms x 128B + 16 pad), B 128 x 400B, bsq 128f.
// Row stride 400 = 3*128+16  =>  16B-offset rotation => conflict-free ldmatrix.
// Global argmin via atomicMin on packed (sortable_dist<<32 | k).
// ---------------------------------------------------------------------------
#define ASTRIDE  400
#define OFF_B_SM (128 * ASTRIDE)            // 51200
#define OFF_BSQ  (2 * 128 * ASTRIDE)        // 102400
#define SMEM_REQ (OFF_BSQ + 512)            // 102912

__global__ void __launch_bounds__(256, 2)
gemm_kernel(const float* __restrict__ cbin, const float* __restrict__ ema,
            float* __restrict__ out)
{
    extern __shared__ char smp[];
    const uint32_t smA = smem_u32(smp);
    const uint32_t smB = smA + OFF_B_SM;
    float* bsqs = (float*)(smp + OFF_BSQ);

    const int t = threadIdx.x, warp = t >> 5, lane = t & 31;
    const int wm = warp >> 2, wn = warp & 3;
    const int mtc = blockIdx.x & 3, ntc = blockIdx.x >> 2;
    const int d  = blockIdx.y;
    const int b0 = mtc * 128, k0 = ntc * 128;
    const int blk = d * 32 + blockIdx.x;     // 0..2047

    // ---- fused output prep (fire-and-forget; hides under other CTA's MMA) ----
    {
        float4 z = make_float4(0.f, 0.f, 0.f, 0.f);
        float4* oh4 = (float4*)(out + OH_OFF);
        size_t base = (size_t)blk * 4096;
        #pragma unroll 4
        for (int it = 0; it < 16; ++it)
            oh4[base + t + it * 256] = z;

        const float4* cb4 = (const float4*)cbin;
        float4* ncb4 = (float4*)(out + NCB_OFF);
        size_t cb0 = (size_t)blk * 512;
        #pragma unroll
        for (int it = 0; it < 2; ++it) {
            float4 v = cb4[cb0 + t + it * 256];
            v.x *= 0.999f; v.y *= 0.999f; v.z *= 0.999f; v.w *= 0.999f;
            ncb4[cb0 + t + it * 256] = v;
        }
        if (t < 8) {
            const float4* em4 = (const float4*)ema;
            float4* ne4 = (float4*)(out + NEMA_OFF);
            size_t eb = (size_t)blk * 8 + t;
            float4 v = em4[eb];
            v.x *= 0.999f; v.y *= 0.999f; v.z *= 0.999f; v.w *= 0.999f;
            ne4[eb] = v;
        }
    }

    // ---- load A, B tiles (3 bf16 split terms each) + bsq ----
    const __nv_bfloat16* xsb = &g_xs[0][0][0][0];
    const __nv_bfloat16* csb = &g_cs[0][0][0][0];
    #pragma unroll
    for (int term = 0; term < 3; ++term) {
        #pragma unroll
        for (int it = 0; it < 4; ++it) {
            int idx = t + it * 256;          // 0..1023
            int row = idx >> 3, seg = idx & 7;
            uint4 va = *(const uint4*)(xsb +
                (((size_t)term * DIMC + d) * BATCH + b0 + row) * EMB + seg * 8);
            *(uint4*)(smp + row * ASTRIDE + term * 128 + seg * 16) = va;
            uint4 vb = *(const uint4*)(csb +
                (((size_t)term * DIMC + d) * BOOK + k0 + row) * EMB + seg * 8);
            *(uint4*)(smp + OFF_B_SM + row * ASTRIDE + term * 128 + seg * 16) = vb;
        }
    }
    if (t < 128) bsqs[t] = g_bsq[d * BOOK + k0 + t];
    __syncthreads();

    // ---- MMA mainloop: 6 passes x 4 ksteps ----
    float acc[4][4][4];
    #pragma unroll
    for (int i = 0; i < 4; ++i)
        #pragma unroll
        for (int j = 0; j < 4; ++j)
            #pragma unroll
            for (int q = 0; q < 4; ++q) acc[i][j][q] = 0.f;

    const int lr = (lane & 7) + ((lane >> 3) & 1) * 8;   // A row within 16
    const int ka = ((lane >> 4) & 1) * 16;               // A k-half byte
    const int nr = (lane & 7) + ((lane >> 4) & 1) * 8;   // B n within 16
    const int kb = ((lane >> 3) & 1) * 16;               // B k-half byte

    const uint32_t aBase = smA + (wm * 64 + lr) * ASTRIDE + ka;
    const uint32_t bBase = smB + (wn * 32 + nr) * ASTRIDE + kb;

    const int TA[6] = {0, 0, 1, 1, 0, 2};
    const int TB[6] = {0, 1, 0, 1, 2, 0};

    #pragma unroll
    for (int p = 0; p < 6; ++p) {
        const uint32_t aT = aBase + TA[p] * 128;
        const uint32_t bT = bBase + TB[p] * 128;
        #pragma unroll
        for (int ks = 0; ks < 4; ++ks) {
            uint32_t af[4][4];
            #pragma unroll
            for (int mt = 0; mt < 4; ++mt)
                LDSM_X4(af[mt][0], af[mt][1], af[mt][2], af[mt][3],
                        aT + mt * (16 * ASTRIDE) + ks * 32);
            uint32_t bf[4][2];
            #pragma unroll
            for (int np = 0; np < 2; ++np)
                LDSM_X4(bf[np * 2][0], bf[np * 2][1],
                        bf[np * 2 + 1][0], bf[np * 2 + 1][1],
                        bT + np * (16 * ASTRIDE) + ks * 32);
            #pragma unroll
            for (int mt = 0; mt < 4; ++mt)
                #pragma unroll
                for (int nt = 0; nt < 4; ++nt)
                    MMA16816(acc[mt][nt], af[mt], bf[nt]);
        }
    }

    // ---- epilogue: dist = bsq - 2*dot, per-row argmin, global atomicMin ----
    #pragma unroll
    for (int mt = 0; mt < 4; ++mt) {
        #pragma unroll
        for (int h = 0; h < 2; ++h) {
            int row = wm * 64 + mt * 16 + (lane >> 2) + h * 8;
            float bd = 3.4e38f;
            int   bk = 0;
            #pragma unroll
            for (int nt = 0; nt < 4; ++nt) {
                #pragma unroll
                for (int j = 0; j < 2; ++j) {
                    int col = wn * 32 + nt * 8 + (lane & 3) * 2 + j;
                    float dist = fmaf(-2.f, acc[mt][nt][h * 2 + j], bsqs[col]);
                    int k = k0 + col;
                    if (dist < bd) { bd = dist; bk = k; }
                }
            }
            #pragma unroll
            for (int off = 1; off <= 2; off <<= 1) {
                float od = __shfl_xor_sync(0xffffffffu, bd, off);
                int   ok = __shfl_xor_sync(0xffffffffu, bk, off);
                if (od < bd || (od == bd && ok < bk)) { bd = od; bk = ok; }
            }
            if ((lane & 3) == 0) {
                uint32_t u = __float_as_uint(bd);
                uint32_t s = (u & 0x80000000u) ? ~u : (u | 0x80000000u);
                unsigned long long key = ((unsigned long long)s << 32) |
                                         (unsigned)bk;
                atomicMin(&g_key[(b0 + row) * DIMC + d], key);
            }
        }
    }
}

// ---------------------------------------------------------------------------
// Kernel 2: gather cw, set one_hot ones, EMA scatter-adds.
// One warp per (b,d); lane handles 2 embedding elements.
// ---------------------------------------------------------------------------
__global__ void __launch_bounds__(256)
scatter_kernel(const float* __restrict__ x, const float* __restrict__ cb,
               const float* __restrict__ ema, float* __restrict__ out)
{
    const float GAINF = (float)(1.0 - 0.999);
    const float EPSF  = 1e-6f;
    float* cw   = out + CW_OFF;
    float* oh   = out + OH_OFF;
    float* ncb  = out + NCB_OFF;
    float* nema = out + NEMA_OFF;

    int b    = blockIdx.x;
    int warp = threadIdx.x >> 5;
    int lane = threadIdx.x & 31;

    #pragma unroll
    for (int dd = 0; dd < 8; ++dd) {
        int d = warp * 8 + dd;
        int k = (int)(unsigned)(g_key[b * DIMC + d] & 0xFFFFFFFFull);
        float g = GAINF / (ema[d * BOOK + k] + EPSF);

        size_t co = ((size_t)d * BOOK + k) * EMB + 2 * lane;
        size_t xo = (size_t)b * CWDIM + d * EMB + 2 * lane;
        float2 c2 = *(const float2*)(cb + co);
        float2 x2 = *(const float2*)(x + xo);

        float2 w;
        w.x = x2.x + (c2.x - x2.x);
        w.y = x2.y + (c2.y - x2.y);
        *(float2*)(cw + xo) = w;

        atomicAdd(ncb + co,     g * x2.x);
        atomicAdd(ncb + co + 1, g * x2.y);

        if (lane == 0) {
            oh[(size_t)b * (DIMC * BOOK) + (size_t)d * BOOK + k] = 1.0f;
            atomicAdd(nema + d * BOOK + k, GAINF);
        }
    }
}

// ---------------------------------------------------------------------------
extern "C" void kernel_launch(void* const* d_in, const int* in_sizes, int n_in,
                              void* d_out, int out_size)
{
    (void)in_sizes; (void)n_in; (void)out_size;
    const float* x   = (const float*)d_in[0];
    const float* cb  = (const float*)d_in[1];
    const float* ema = (const float*)d_in[2];
    float* out = (float*)d_out;

    cudaFuncSetAttribute(gemm_kernel,
                         cudaFuncAttributeMaxDynamicSharedMemorySize, SMEM_REQ);

    split_kernel<<<12288, 256>>>(x, cb);
    dim3 grid(32, 64);   // 4 M-tiles x 8 N-tiles, 64 dims
    gemm_kernel<<<grid, 256, SMEM_REQ>>>(cb, ema, out);
    scatter_kernel<<<BATCH, 256>>>(x, cb, ema, out);
}